// round 11
// baseline (speedup 1.0000x reference)
#include <cuda_runtime.h>
#include <cstdint>

// Problem constants
#define GM 9600          // B*Lq = 32*300
#define GK 256           // D_MODEL
#define NRAW 288         // 192 offset cols + 96 attn cols
#define BM 64
#define BN 96
#define BK 32

#define NCHUNK 5
#define CHUNK_ROWS 1920          // 1920 = 64*30; 9600 = 5*1920

// Scratch for raw GEMM output (query @ [W_off | W_attn] + bias), ~11 MB.
__device__ float g_raw[GM * NRAW];

// ---------------------------------------------------------------------------
// Kernel 1: fused GEMM  raw[rows][288] = query @ [W_off(192) | W_attn(96)] + b
// R8 configuration (best measured): double-buffered SMEM fp32, 4m x 6n
// microtile, BM=64 BN=96 BK=32, 256 threads as 16x16. Per-chunk grid (30,3).
// ---------------------------------------------------------------------------
__global__ __launch_bounds__(256) void dfine_gemm_kernel(
    const float* __restrict__ A,      // query (9600 x 256)
    const float* __restrict__ Woff,   // (256 x 192)
    const float* __restrict__ boff,   // (192)
    const float* __restrict__ Wattn,  // (256 x 96)
    const float* __restrict__ battn,  // (96)
    int chunkBase)                    // first row of this chunk
{
    __shared__ float As[2][BK][68];   // padded: 16B-aligned float4 rows, no STS conflict
    __shared__ float Bs[2][BK][BN];

    const int tid  = threadIdx.x;
    const int rowBase = chunkBase + blockIdx.x * BM;
    const int nblk = blockIdx.y;

    const float* Bsrc;
    const float* bias;
    int ldB, colBase, nGlobalBase;
    if (nblk < 2) { Bsrc = Woff;  bias = boff;  ldB = 192; colBase = nblk * 96; nGlobalBase = nblk * 96; }
    else          { Bsrc = Wattn; bias = battn; ldB = 96;  colBase = 0;         nGlobalBase = 192; }

    const int ty = tid >> 4;   // 0..15 (m)
    const int tx = tid & 15;   // 0..15 (n)

    // A-load mapping (2 float4 per thread)
    const int fA0 = tid;
    const int rA0 = fA0 >> 3, kqA0 = fA0 & 7;
    const int fA1 = tid + 256;
    const int rA1 = fA1 >> 3, kqA1 = fA1 & 7;

    float acc[4][6];
    #pragma unroll
    for (int i = 0; i < 4; i++)
        #pragma unroll
        for (int j = 0; j < 6; j++) acc[i][j] = 0.0f;

    float4 avr[2];
    float  bvr[12];

    // ---- prologue: load tile 0 into regs, store to buf 0
    {
        avr[0] = *reinterpret_cast<const float4*>(A + (rowBase + rA0) * GK + kqA0 * 4);
        avr[1] = *reinterpret_cast<const float4*>(A + (rowBase + rA1) * GK + kqA1 * 4);
        #pragma unroll
        for (int i = 0; i < 12; i++) {
            int e = tid + i * 256;
            int k = e / 96;
            int n = e - k * 96;
            bvr[i] = __ldg(Bsrc + k * ldB + colBase + n);
        }
        As[0][kqA0 * 4 + 0][rA0] = avr[0].x;
        As[0][kqA0 * 4 + 1][rA0] = avr[0].y;
        As[0][kqA0 * 4 + 2][rA0] = avr[0].z;
        As[0][kqA0 * 4 + 3][rA0] = avr[0].w;
        As[0][kqA1 * 4 + 0][rA1] = avr[1].x;
        As[0][kqA1 * 4 + 1][rA1] = avr[1].y;
        As[0][kqA1 * 4 + 2][rA1] = avr[1].z;
        As[0][kqA1 * 4 + 3][rA1] = avr[1].w;
        #pragma unroll
        for (int i = 0; i < 12; i++) {
            int e = tid + i * 256;
            int k = e / 96;
            int n = e - k * 96;
            Bs[0][k][n] = bvr[i];
        }
    }
    __syncthreads();

    const int NT = GK / BK;   // 8 tiles
    for (int t = 0; t < NT; t++) {
        const int cur = t & 1;
        if (t + 1 < NT) {
            const int k0 = (t + 1) * BK;
            avr[0] = *reinterpret_cast<const float4*>(A + (rowBase + rA0) * GK + k0 + kqA0 * 4);
            avr[1] = *reinterpret_cast<const float4*>(A + (rowBase + rA1) * GK + k0 + kqA1 * 4);
            #pragma unroll
            for (int i = 0; i < 12; i++) {
                int e = tid + i * 256;
                int k = e / 96;
                int n = e - k * 96;
                bvr[i] = __ldg(Bsrc + (k0 + k) * ldB + colBase + n);
            }
        }

        #pragma unroll
        for (int k = 0; k < BK; k++) {
            float4 av = *reinterpret_cast<const float4*>(&As[cur][k][ty * 4]);
            float a[4] = {av.x, av.y, av.z, av.w};
            float bv[6];
            float2 b0 = *reinterpret_cast<const float2*>(&Bs[cur][k][tx * 6 + 0]);
            float2 b1 = *reinterpret_cast<const float2*>(&Bs[cur][k][tx * 6 + 2]);
            float2 b2 = *reinterpret_cast<const float2*>(&Bs[cur][k][tx * 6 + 4]);
            bv[0] = b0.x; bv[1] = b0.y; bv[2] = b1.x; bv[3] = b1.y; bv[4] = b2.x; bv[5] = b2.y;
            #pragma unroll
            for (int i = 0; i < 4; i++)
                #pragma unroll
                for (int j = 0; j < 6; j++)
                    acc[i][j] = fmaf(a[i], bv[j], acc[i][j]);
        }

        if (t + 1 < NT) {
            const int nxt = 1 - cur;
            As[nxt][kqA0 * 4 + 0][rA0] = avr[0].x;
            As[nxt][kqA0 * 4 + 1][rA0] = avr[0].y;
            As[nxt][kqA0 * 4 + 2][rA0] = avr[0].z;
            As[nxt][kqA0 * 4 + 3][rA0] = avr[0].w;
            As[nxt][kqA1 * 4 + 0][rA1] = avr[1].x;
            As[nxt][kqA1 * 4 + 1][rA1] = avr[1].y;
            As[nxt][kqA1 * 4 + 2][rA1] = avr[1].z;
            As[nxt][kqA1 * 4 + 3][rA1] = avr[1].w;
            #pragma unroll
            for (int i = 0; i < 12; i++) {
                int e = tid + i * 256;
                int k = e / 96;
                int n = e - k * 96;
                Bs[nxt][k][n] = bvr[i];
            }
        }
        __syncthreads();
    }

    // ---- epilogue: add bias, write to g_raw
    #pragma unroll
    for (int i = 0; i < 4; i++) {
        int r = rowBase + ty * 4 + i;
        #pragma unroll
        for (int j = 0; j < 6; j++) {
            int n = tx * 6 + j;
            g_raw[r * NRAW + nGlobalBase + n] = acc[i][j] + __ldg(bias + colBase + n);
        }
    }
}

// ---------------------------------------------------------------------------
// Kernel 2: fused softmax + location transform + bilinear gather + weighted sum
// (R8 version — predicated corner loads; measured 43.7/43.2 us.)
// Block = 256 threads = 4 queries x 64 threads; thread = 4 channels (float4).
// ---------------------------------------------------------------------------
__global__ __launch_bounds__(256) void dfine_sample_kernel(
    const float* __restrict__ refp,   // (32,300,1,4)
    const float* __restrict__ value,  // input_flatten (32, 8400, 256)
    float* __restrict__ out,          // (32,300,256)
    int chunkBase)                    // first row of this chunk
{
    __shared__ int   sOffs[4][96][4];  // absolute spatial index (0..8399) or -1
    __shared__ float sWts[4][96][4];   // bilinear weights * softmax weight
    __shared__ float sLog[4][96];      // attn logits -> probabilities

    const int tid  = threadIdx.x;
    const int row0 = chunkBase + blockIdx.x * 4;  // chunk multiple of 4; never straddles batch

    // ---- Phase A: per-(query,head,point) address/weight precompute
    #pragma unroll
    for (int e = tid; e < 384; e += 256) {
        int qi = e / 96, j = e % 96;       // j = h*12 + pt
        int row = row0 + qi;
        const float* raw = g_raw + (size_t)row * NRAW;
        float rx = __ldg(refp + row * 4 + 0);
        float ry = __ldg(refp + row * 4 + 1);
        float rw = __ldg(refp + row * 4 + 2);
        float rh = __ldg(refp + row * 4 + 3);
        float ox = raw[2 * j + 0];
        float oy = raw[2 * j + 1];
        sLog[qi][j] = raw[192 + j];

        int pt  = j % 12;
        int lvl = pt >> 2;
        int   W    = (lvl == 0) ? 80 : (lvl == 1) ? 40 : 20;  // H == W
        int   loff = (lvl == 0) ? 0  : (lvl == 1) ? 6400 : 8000;
        float Wf   = (float)W;
        // pscale=1/4, OFFSET_SCALE=0.5 -> 0.125; pixel = loc*W - 0.5
        float ix = (rx + ox * 0.125f * rw) * Wf - 0.5f;
        float iy = (ry + oy * 0.125f * rh) * Wf - 0.5f;
        float fx0 = floorf(ix), fy0 = floorf(iy);
        float fx = ix - fx0, fy = iy - fy0;
        int x0 = (int)fx0, y0 = (int)fy0;
        int x1 = x0 + 1,   y1 = y0 + 1;
        bool vx0 = (unsigned)x0 < (unsigned)W;
        bool vx1 = (unsigned)x1 < (unsigned)W;
        bool vy0 = (unsigned)y0 < (unsigned)W;
        bool vy1 = (unsigned)y1 < (unsigned)W;
        sOffs[qi][j][0] = (vx0 && vy0) ? (loff + y0 * W + x0) : -1;
        sOffs[qi][j][1] = (vx1 && vy0) ? (loff + y0 * W + x1) : -1;
        sOffs[qi][j][2] = (vx0 && vy1) ? (loff + y1 * W + x0) : -1;
        sOffs[qi][j][3] = (vx1 && vy1) ? (loff + y1 * W + x1) : -1;
        float gx = 1.0f - fx, gy = 1.0f - fy;
        sWts[qi][j][0] = gx * gy;
        sWts[qi][j][1] = fx * gy;
        sWts[qi][j][2] = gx * fy;
        sWts[qi][j][3] = fx * fy;
    }
    __syncthreads();

    // ---- Phase B: per-(query,head) softmax over 12 points (in place)
    if (tid < 32) {
        int qi = tid >> 3, h = tid & 7;
        float* L = &sLog[qi][h * 12];
        float m = -1e30f;
        #pragma unroll
        for (int p = 0; p < 12; p++) m = fmaxf(m, L[p]);
        float s = 0.0f;
        #pragma unroll
        for (int p = 0; p < 12; p++) { float ev = expf(L[p] - m); L[p] = ev; s += ev; }
        float inv = 1.0f / s;
        #pragma unroll
        for (int p = 0; p < 12; p++) L[p] *= inv;
    }
    __syncthreads();

    // ---- Phase C: fold softmax weight into bilinear weights
    #pragma unroll
    for (int e = tid; e < 384; e += 256) {
        int qi = e / 96, j = e % 96;
        float w = sLog[qi][j];
        sWts[qi][j][0] *= w;
        sWts[qi][j][1] *= w;
        sWts[qi][j][2] *= w;
        sWts[qi][j][3] *= w;
    }
    __syncthreads();

    // ---- Phase D: gather + accumulate. 64 threads/query, float4 channels.
    const int qi   = tid >> 6;         // query within block
    const int lane = tid & 63;         // channel-quad index 0..63
    const int h    = lane >> 3;        // head (8 channel-quads per head)
    const int row  = row0 + qi;
    const int b    = row / 300;

    const float4* __restrict__ vb =
        (const float4*)value + (size_t)b * 8400 * 64 + h * 8 + (lane & 7);

    float4 acc = make_float4(0.0f, 0.0f, 0.0f, 0.0f);
    #pragma unroll 4
    for (int pt = 0; pt < 12; pt++) {
        int j = h * 12 + pt;
        int4   o = *reinterpret_cast<const int4*>(sOffs[qi][j]);
        float4 w = *reinterpret_cast<const float4*>(sWts[qi][j]);
        if (o.x >= 0) {
            float4 v = __ldg(vb + (size_t)o.x * 64);
            acc.x += w.x * v.x; acc.y += w.x * v.y; acc.z += w.x * v.z; acc.w += w.x * v.w;
        }
        if (o.y >= 0) {
            float4 v = __ldg(vb + (size_t)o.y * 64);
            acc.x += w.y * v.x; acc.y += w.y * v.y; acc.z += w.y * v.z; acc.w += w.y * v.w;
        }
        if (o.z >= 0) {
            float4 v = __ldg(vb + (size_t)o.z * 64);
            acc.x += w.z * v.x; acc.y += w.z * v.y; acc.z += w.z * v.z; acc.w += w.z * v.w;
        }
        if (o.w >= 0) {
            float4 v = __ldg(vb + (size_t)o.w * 64);
            acc.x += w.w * v.x; acc.y += w.w * v.y; acc.z += w.w * v.z; acc.w += w.w * v.w;
        }
    }

    reinterpret_cast<float4*>(out)[(size_t)row * 64 + lane] = acc;
}

// ---------------------------------------------------------------------------
// Launch: chunked GEMM->sampler pipeline across two streams so the fma-bound
// GEMM and the DRAM/latency-bound sampler overlap. GEMM chunks run on the
// default (captured) stream; each sampler chunk runs on a forked stream gated
// by an event recorded after its GEMM chunk; a final event joins back.
// Streams/events are created once on the first (uncaptured) call, so every
// call enqueues identical work.
//
// Inputs in metadata order:
//   0 query (32,300,256) f32        1 reference_points (32,300,1,4) f32
//   2 input_flatten (32,8400,256)   3 W_off (256,192)   4 b_off (192)
//   5 W_attn (256,96)               6 b_attn (96)
// Output: (32,300,256) f32
// ---------------------------------------------------------------------------
extern "C" void kernel_launch(void* const* d_in, const int* in_sizes, int n_in,
                              void* d_out, int out_size) {
    const float* query = (const float*)d_in[0];
    const float* refp  = (const float*)d_in[1];
    const float* value = (const float*)d_in[2];
    const float* Woff  = (const float*)d_in[3];
    const float* boff  = (const float*)d_in[4];
    const float* Wattn = (const float*)d_in[5];
    const float* battn = (const float*)d_in[6];
    float* out = (float*)d_out;

    static cudaStream_t s2 = nullptr;
    static cudaEvent_t evG[NCHUNK];
    static cudaEvent_t evJoin = nullptr;
    if (s2 == nullptr) {
        cudaStreamCreateWithFlags(&s2, cudaStreamNonBlocking);
        for (int c = 0; c < NCHUNK; c++)
            cudaEventCreateWithFlags(&evG[c], cudaEventDisableTiming);
        cudaEventCreateWithFlags(&evJoin, cudaEventDisableTiming);
    }

    dim3 ggrid(CHUNK_ROWS / BM, 3);        // 30 x 3 per chunk
    const int sblocks = CHUNK_ROWS / 4;    // 480 per chunk

    for (int c = 0; c < NCHUNK; c++) {
        int base = c * CHUNK_ROWS;
        dfine_gemm_kernel<<<ggrid, 256, 0, 0>>>(query, Woff, boff, Wattn, battn, base);
        cudaEventRecord(evG[c], 0);
        cudaStreamWaitEvent(s2, evG[c], 0);
        dfine_sample_kernel<<<sblocks, 256, 0, s2>>>(refp, value, out, base);
    }
    cudaEventRecord(evJoin, s2);
    cudaStreamWaitEvent(0, evJoin, 0);
}

// round 16
// speedup vs baseline: 1.2606x; 1.2606x over previous
#include <cuda_runtime.h>
#include <cstdint>

// Problem constants
#define GM 9600          // B*Lq = 32*300
#define GK 256           // D_MODEL
#define NRAW 288         // 192 offset cols + 96 attn cols
#define BM 64
#define BN 96
#define BK 32

#define CHUNK_ROWS 4800          // 9600 = 2*4800; 4800 = 64*75 = 4*1200
#define GEMM_BLKS 225            // 75 x 3 (flattened) per chunk
#define SAMP_BLKS 1200           // 4800 / 4 per chunk

// Scratch for raw GEMM output (query @ [W_off | W_attn] + bias), ~11 MB.
__device__ float g_raw[GM * NRAW];

// ---- SMEM overlays (union'd in the fat kernel) ----
struct GemmSmem {
    float As[2][BK][68];   // padded: 16B-aligned float4 rows, no STS conflict
    float Bs[2][BK][BN];
};                          // 41984 bytes
struct SampSmem {
    int   sOffs[4][96][4];  // absolute spatial index (0..8399) or -1
    float sWts[4][96][4];   // bilinear weights * softmax weight
    float sLog[4][96];      // attn logits -> probabilities
};                          // 13824 bytes
#define SMEM_MAX 41984

// ---------------------------------------------------------------------------
// GEMM body (R8 config, measured 44.8us at 450 blocks): double-buffered SMEM
// fp32, 4m x 6n microtile, BM=64 BN=96 BK=32, 256 threads as 16x16.
// ---------------------------------------------------------------------------
__device__ __forceinline__ void gemm_body(
    GemmSmem* sm,
    const float* __restrict__ A,
    const float* __restrict__ Woff,
    const float* __restrict__ boff,
    const float* __restrict__ Wattn,
    const float* __restrict__ battn,
    int rowBase, int nblk)
{
    const int tid = threadIdx.x;

    const float* Bsrc;
    const float* bias;
    int ldB, colBase, nGlobalBase;
    if (nblk < 2) { Bsrc = Woff;  bias = boff;  ldB = 192; colBase = nblk * 96; nGlobalBase = nblk * 96; }
    else          { Bsrc = Wattn; bias = battn; ldB = 96;  colBase = 0;         nGlobalBase = 192; }

    const int ty = tid >> 4;   // 0..15 (m)
    const int tx = tid & 15;   // 0..15 (n)

    const int fA0 = tid;
    const int rA0 = fA0 >> 3, kqA0 = fA0 & 7;
    const int fA1 = tid + 256;
    const int rA1 = fA1 >> 3, kqA1 = fA1 & 7;

    float acc[4][6];
    #pragma unroll
    for (int i = 0; i < 4; i++)
        #pragma unroll
        for (int j = 0; j < 6; j++) acc[i][j] = 0.0f;

    float4 avr[2];
    float  bvr[12];

    // ---- prologue: tile 0 -> buf 0
    {
        avr[0] = *reinterpret_cast<const float4*>(A + (rowBase + rA0) * GK + kqA0 * 4);
        avr[1] = *reinterpret_cast<const float4*>(A + (rowBase + rA1) * GK + kqA1 * 4);
        #pragma unroll
        for (int i = 0; i < 12; i++) {
            int e = tid + i * 256;
            int k = e / 96;
            int n = e - k * 96;
            bvr[i] = __ldg(Bsrc + k * ldB + colBase + n);
        }
        sm->As[0][kqA0 * 4 + 0][rA0] = avr[0].x;
        sm->As[0][kqA0 * 4 + 1][rA0] = avr[0].y;
        sm->As[0][kqA0 * 4 + 2][rA0] = avr[0].z;
        sm->As[0][kqA0 * 4 + 3][rA0] = avr[0].w;
        sm->As[0][kqA1 * 4 + 0][rA1] = avr[1].x;
        sm->As[0][kqA1 * 4 + 1][rA1] = avr[1].y;
        sm->As[0][kqA1 * 4 + 2][rA1] = avr[1].z;
        sm->As[0][kqA1 * 4 + 3][rA1] = avr[1].w;
        #pragma unroll
        for (int i = 0; i < 12; i++) {
            int e = tid + i * 256;
            int k = e / 96;
            int n = e - k * 96;
            sm->Bs[0][k][n] = bvr[i];
        }
    }
    __syncthreads();

    const int NT = GK / BK;   // 8 tiles
    for (int t = 0; t < NT; t++) {
        const int cur = t & 1;
        if (t + 1 < NT) {
            const int k0 = (t + 1) * BK;
            avr[0] = *reinterpret_cast<const float4*>(A + (rowBase + rA0) * GK + k0 + kqA0 * 4);
            avr[1] = *reinterpret_cast<const float4*>(A + (rowBase + rA1) * GK + k0 + kqA1 * 4);
            #pragma unroll
            for (int i = 0; i < 12; i++) {
                int e = tid + i * 256;
                int k = e / 96;
                int n = e - k * 96;
                bvr[i] = __ldg(Bsrc + (k0 + k) * ldB + colBase + n);
            }
        }

        #pragma unroll
        for (int k = 0; k < BK; k++) {
            float4 av = *reinterpret_cast<const float4*>(&sm->As[cur][k][ty * 4]);
            float a[4] = {av.x, av.y, av.z, av.w};
            float bv[6];
            float2 b0 = *reinterpret_cast<const float2*>(&sm->Bs[cur][k][tx * 6 + 0]);
            float2 b1 = *reinterpret_cast<const float2*>(&sm->Bs[cur][k][tx * 6 + 2]);
            float2 b2 = *reinterpret_cast<const float2*>(&sm->Bs[cur][k][tx * 6 + 4]);
            bv[0] = b0.x; bv[1] = b0.y; bv[2] = b1.x; bv[3] = b1.y; bv[4] = b2.x; bv[5] = b2.y;
            #pragma unroll
            for (int i = 0; i < 4; i++)
                #pragma unroll
                for (int j = 0; j < 6; j++)
                    acc[i][j] = fmaf(a[i], bv[j], acc[i][j]);
        }

        if (t + 1 < NT) {
            const int nxt = 1 - cur;
            sm->As[nxt][kqA0 * 4 + 0][rA0] = avr[0].x;
            sm->As[nxt][kqA0 * 4 + 1][rA0] = avr[0].y;
            sm->As[nxt][kqA0 * 4 + 2][rA0] = avr[0].z;
            sm->As[nxt][kqA0 * 4 + 3][rA0] = avr[0].w;
            sm->As[nxt][kqA1 * 4 + 0][rA1] = avr[1].x;
            sm->As[nxt][kqA1 * 4 + 1][rA1] = avr[1].y;
            sm->As[nxt][kqA1 * 4 + 2][rA1] = avr[1].z;
            sm->As[nxt][kqA1 * 4 + 3][rA1] = avr[1].w;
            #pragma unroll
            for (int i = 0; i < 12; i++) {
                int e = tid + i * 256;
                int k = e / 96;
                int n = e - k * 96;
                sm->Bs[nxt][k][n] = bvr[i];
            }
        }
        __syncthreads();
    }

    // ---- epilogue: add bias, write to g_raw
    #pragma unroll
    for (int i = 0; i < 4; i++) {
        int r = rowBase + ty * 4 + i;
        #pragma unroll
        for (int j = 0; j < 6; j++) {
            int n = tx * 6 + j;
            g_raw[r * NRAW + nGlobalBase + n] = acc[i][j] + __ldg(bias + colBase + n);
        }
    }
}

// ---------------------------------------------------------------------------
// Sampler body (R8 version, measured 43.2us at 2400 blocks): softmax +
// location transform + bilinear gather + weighted sum. 256 threads =
// 4 queries x 64 threads; thread = 4 channels (float4); predicated corners.
// ---------------------------------------------------------------------------
__device__ __forceinline__ void sample_body(
    SampSmem* sm,
    const float* __restrict__ refp,
    const float* __restrict__ value,
    float* __restrict__ out,
    int row0)
{
    const int tid = threadIdx.x;

    // ---- Phase A: per-(query,head,point) address/weight precompute
    #pragma unroll
    for (int e = tid; e < 384; e += 256) {
        int qi = e / 96, j = e % 96;       // j = h*12 + pt
        int row = row0 + qi;
        const float* raw = g_raw + (size_t)row * NRAW;
        float rx = __ldg(refp + row * 4 + 0);
        float ry = __ldg(refp + row * 4 + 1);
        float rw = __ldg(refp + row * 4 + 2);
        float rh = __ldg(refp + row * 4 + 3);
        float ox = raw[2 * j + 0];
        float oy = raw[2 * j + 1];
        sm->sLog[qi][j] = raw[192 + j];

        int pt  = j % 12;
        int lvl = pt >> 2;
        int   W    = (lvl == 0) ? 80 : (lvl == 1) ? 40 : 20;  // H == W
        int   loff = (lvl == 0) ? 0  : (lvl == 1) ? 6400 : 8000;
        float Wf   = (float)W;
        // pscale=1/4, OFFSET_SCALE=0.5 -> 0.125; pixel = loc*W - 0.5
        float ix = (rx + ox * 0.125f * rw) * Wf - 0.5f;
        float iy = (ry + oy * 0.125f * rh) * Wf - 0.5f;
        float fx0 = floorf(ix), fy0 = floorf(iy);
        float fx = ix - fx0, fy = iy - fy0;
        int x0 = (int)fx0, y0 = (int)fy0;
        int x1 = x0 + 1,   y1 = y0 + 1;
        bool vx0 = (unsigned)x0 < (unsigned)W;
        bool vx1 = (unsigned)x1 < (unsigned)W;
        bool vy0 = (unsigned)y0 < (unsigned)W;
        bool vy1 = (unsigned)y1 < (unsigned)W;
        sm->sOffs[qi][j][0] = (vx0 && vy0) ? (loff + y0 * W + x0) : -1;
        sm->sOffs[qi][j][1] = (vx1 && vy0) ? (loff + y0 * W + x1) : -1;
        sm->sOffs[qi][j][2] = (vx0 && vy1) ? (loff + y1 * W + x0) : -1;
        sm->sOffs[qi][j][3] = (vx1 && vy1) ? (loff + y1 * W + x1) : -1;
        float gx = 1.0f - fx, gy = 1.0f - fy;
        sm->sWts[qi][j][0] = gx * gy;
        sm->sWts[qi][j][1] = fx * gy;
        sm->sWts[qi][j][2] = gx * fy;
        sm->sWts[qi][j][3] = fx * fy;
    }
    __syncthreads();

    // ---- Phase B: per-(query,head) softmax over 12 points (in place)
    if (tid < 32) {
        int qi = tid >> 3, h = tid & 7;
        float* L = &sm->sLog[qi][h * 12];
        float m = -1e30f;
        #pragma unroll
        for (int p = 0; p < 12; p++) m = fmaxf(m, L[p]);
        float s = 0.0f;
        #pragma unroll
        for (int p = 0; p < 12; p++) { float ev = expf(L[p] - m); L[p] = ev; s += ev; }
        float inv = 1.0f / s;
        #pragma unroll
        for (int p = 0; p < 12; p++) L[p] *= inv;
    }
    __syncthreads();

    // ---- Phase C: fold softmax weight into bilinear weights
    #pragma unroll
    for (int e = tid; e < 384; e += 256) {
        int qi = e / 96, j = e % 96;
        float w = sm->sLog[qi][j];
        sm->sWts[qi][j][0] *= w;
        sm->sWts[qi][j][1] *= w;
        sm->sWts[qi][j][2] *= w;
        sm->sWts[qi][j][3] *= w;
    }
    __syncthreads();

    // ---- Phase D: gather + accumulate. 64 threads/query, float4 channels.
    const int qi   = tid >> 6;         // query within block
    const int lane = tid & 63;         // channel-quad index 0..63
    const int h    = lane >> 3;        // head (8 channel-quads per head)
    const int row  = row0 + qi;
    const int b    = row / 300;

    const float4* __restrict__ vb =
        (const float4*)value + (size_t)b * 8400 * 64 + h * 8 + (lane & 7);

    float4 acc = make_float4(0.0f, 0.0f, 0.0f, 0.0f);
    #pragma unroll 4
    for (int pt = 0; pt < 12; pt++) {
        int j = h * 12 + pt;
        int4   o = *reinterpret_cast<const int4*>(sm->sOffs[qi][j]);
        float4 w = *reinterpret_cast<const float4*>(sm->sWts[qi][j]);
        if (o.x >= 0) {
            float4 v = __ldg(vb + (size_t)o.x * 64);
            acc.x += w.x * v.x; acc.y += w.x * v.y; acc.z += w.x * v.z; acc.w += w.x * v.w;
        }
        if (o.y >= 0) {
            float4 v = __ldg(vb + (size_t)o.y * 64);
            acc.x += w.y * v.x; acc.y += w.y * v.y; acc.z += w.y * v.z; acc.w += w.y * v.w;
        }
        if (o.z >= 0) {
            float4 v = __ldg(vb + (size_t)o.z * 64);
            acc.x += w.z * v.x; acc.y += w.z * v.y; acc.z += w.z * v.z; acc.w += w.z * v.w;
        }
        if (o.w >= 0) {
            float4 v = __ldg(vb + (size_t)o.w * 64);
            acc.x += w.w * v.x; acc.y += w.w * v.y; acc.z += w.w * v.z; acc.w += w.w * v.w;
        }
    }

    reinterpret_cast<float4*>(out)[(size_t)row * 64 + lane] = acc;
}

// ---------------------------------------------------------------------------
// Wrapper kernels (single stream, three launches):
//   1) GEMM on chunk0                      (225 blocks)
//   2) FAT kernel: GEMM chunk1 + sampler chunk0 co-scheduled  (1425 blocks)
//   3) sampler on chunk1                   (1200 blocks)
// ---------------------------------------------------------------------------
__global__ __launch_bounds__(256) void dfine_gemm0_kernel(
    const float* __restrict__ A, const float* __restrict__ Woff,
    const float* __restrict__ boff, const float* __restrict__ Wattn,
    const float* __restrict__ battn)
{
    __shared__ GemmSmem sm;
    int xg = blockIdx.x % 75, nblk = blockIdx.x / 75;
    gemm_body(&sm, A, Woff, boff, Wattn, battn, xg * BM, nblk);
}

__global__ __launch_bounds__(256) void dfine_mid_kernel(
    const float* __restrict__ A, const float* __restrict__ Woff,
    const float* __restrict__ boff, const float* __restrict__ Wattn,
    const float* __restrict__ battn,
    const float* __restrict__ refp, const float* __restrict__ value,
    float* __restrict__ out)
{
    __shared__ __align__(16) char smraw[SMEM_MAX];
    const int bx = blockIdx.x;
    if (bx < GEMM_BLKS) {
        // GEMM on chunk1 (rows 4800..9599)
        int xg = bx % 75, nblk = bx / 75;
        gemm_body(reinterpret_cast<GemmSmem*>(smraw),
                  A, Woff, boff, Wattn, battn, CHUNK_ROWS + xg * BM, nblk);
    } else {
        // sampler on chunk0 (rows 0..4799)
        int sx = bx - GEMM_BLKS;
        sample_body(reinterpret_cast<SampSmem*>(smraw),
                    refp, value, out, sx * 4);
    }
}

__global__ __launch_bounds__(256) void dfine_samp1_kernel(
    const float* __restrict__ refp, const float* __restrict__ value,
    float* __restrict__ out)
{
    __shared__ SampSmem sm;
    sample_body(&sm, refp, value, out, CHUNK_ROWS + blockIdx.x * 4);
}

// ---------------------------------------------------------------------------
// Launch: inputs in metadata order:
//   0 query (32,300,256) f32        1 reference_points (32,300,1,4) f32
//   2 input_flatten (32,8400,256)   3 W_off (256,192)   4 b_off (192)
//   5 W_attn (256,96)               6 b_attn (96)
// Output: (32,300,256) f32
// ---------------------------------------------------------------------------
extern "C" void kernel_launch(void* const* d_in, const int* in_sizes, int n_in,
                              void* d_out, int out_size) {
    const float* query = (const float*)d_in[0];
    const float* refp  = (const float*)d_in[1];
    const float* value = (const float*)d_in[2];
    const float* Woff  = (const float*)d_in[3];
    const float* boff  = (const float*)d_in[4];
    const float* Wattn = (const float*)d_in[5];
    const float* battn = (const float*)d_in[6];
    float* out = (float*)d_out;

    dfine_gemm0_kernel<<<GEMM_BLKS, 256>>>(query, Woff, boff, Wattn, battn);
    dfine_mid_kernel<<<GEMM_BLKS + SAMP_BLKS, 256>>>(query, Woff, boff, Wattn,
                                                     battn, refp, value, out);
    dfine_samp1_kernel<<<SAMP_BLKS, 256>>>(refp, value, out);
}

// round 17
// speedup vs baseline: 1.4249x; 1.1303x over previous
#include <cuda_runtime.h>
#include <cstdint>

// Problem constants
#define GM 9600          // B*Lq = 32*300
#define GK 256           // D_MODEL
#define NRAW 288         // 192 offset cols + 96 attn cols
#define BM 64
#define BN 96
#define BK 32

// Scratch for raw GEMM output (query @ [W_off | W_attn] + bias), ~11 MB.
__device__ float g_raw[GM * NRAW];

// Branch-free predicated vector load: @p LDG.128, zero-filled when !p.
// No BSSY/BSYNC region -> ptxas can batch these across the unrolled loop,
// restoring memory-level parallelism that C++ `if` guards destroy.
__device__ __forceinline__ float4 ldg_cond(const float4* ptr, int off) {
    float4 v;
    asm("{\n\t"
        ".reg .pred p;\n\t"
        "setp.ge.s32 p, %5, 0;\n\t"
        "mov.f32 %0, 0f00000000;\n\t"
        "mov.f32 %1, 0f00000000;\n\t"
        "mov.f32 %2, 0f00000000;\n\t"
        "mov.f32 %3, 0f00000000;\n\t"
        "@p ld.global.nc.v4.f32 {%0, %1, %2, %3}, [%4];\n\t"
        "}"
        : "=f"(v.x), "=f"(v.y), "=f"(v.z), "=f"(v.w)
        : "l"(ptr), "r"(off));
    return v;
}

// ---------------------------------------------------------------------------
// Kernel 1: fused GEMM  raw[9600][288] = query @ [W_off(192) | W_attn(96)] + b
// R8 configuration, byte-identical (measured 44.8 us, ~92% of the scalar
// FFMA-pipe floor): double-buffered SMEM fp32, 4m x 6n microtile,
// BM=64 BN=96 BK=32, 256 threads as 16x16, grid (150, 3) = 450 blocks.
// ---------------------------------------------------------------------------
__global__ __launch_bounds__(256) void dfine_gemm_kernel(
    const float* __restrict__ A,      // query (9600 x 256)
    const float* __restrict__ Woff,   // (256 x 192)
    const float* __restrict__ boff,   // (192)
    const float* __restrict__ Wattn,  // (256 x 96)
    const float* __restrict__ battn)  // (96)
{
    __shared__ float As[2][BK][68];   // padded: 16B-aligned float4 rows, no STS conflict
    __shared__ float Bs[2][BK][BN];

    const int tid  = threadIdx.x;
    const int rowBase = blockIdx.x * BM;
    const int nblk = blockIdx.y;

    const float* Bsrc;
    const float* bias;
    int ldB, colBase, nGlobalBase;
    if (nblk < 2) { Bsrc = Woff;  bias = boff;  ldB = 192; colBase = nblk * 96; nGlobalBase = nblk * 96; }
    else          { Bsrc = Wattn; bias = battn; ldB = 96;  colBase = 0;         nGlobalBase = 192; }

    const int ty = tid >> 4;   // 0..15 (m)
    const int tx = tid & 15;   // 0..15 (n)

    // A-load mapping (2 float4 per thread)
    const int fA0 = tid;
    const int rA0 = fA0 >> 3, kqA0 = fA0 & 7;
    const int fA1 = tid + 256;
    const int rA1 = fA1 >> 3, kqA1 = fA1 & 7;

    float acc[4][6];
    #pragma unroll
    for (int i = 0; i < 4; i++)
        #pragma unroll
        for (int j = 0; j < 6; j++) acc[i][j] = 0.0f;

    float4 avr[2];
    float  bvr[12];

    // ---- prologue: load tile 0 into regs, store to buf 0
    {
        avr[0] = *reinterpret_cast<const float4*>(A + (rowBase + rA0) * GK + kqA0 * 4);
        avr[1] = *reinterpret_cast<const float4*>(A + (rowBase + rA1) * GK + kqA1 * 4);
        #pragma unroll
        for (int i = 0; i < 12; i++) {
            int e = tid + i * 256;
            int k = e / 96;
            int n = e - k * 96;
            bvr[i] = __ldg(Bsrc + k * ldB + colBase + n);
        }
        As[0][kqA0 * 4 + 0][rA0] = avr[0].x;
        As[0][kqA0 * 4 + 1][rA0] = avr[0].y;
        As[0][kqA0 * 4 + 2][rA0] = avr[0].z;
        As[0][kqA0 * 4 + 3][rA0] = avr[0].w;
        As[0][kqA1 * 4 + 0][rA1] = avr[1].x;
        As[0][kqA1 * 4 + 1][rA1] = avr[1].y;
        As[0][kqA1 * 4 + 2][rA1] = avr[1].z;
        As[0][kqA1 * 4 + 3][rA1] = avr[1].w;
        #pragma unroll
        for (int i = 0; i < 12; i++) {
            int e = tid + i * 256;
            int k = e / 96;
            int n = e - k * 96;
            Bs[0][k][n] = bvr[i];
        }
    }
    __syncthreads();

    const int NT = GK / BK;   // 8 tiles
    for (int t = 0; t < NT; t++) {
        const int cur = t & 1;
        if (t + 1 < NT) {
            const int k0 = (t + 1) * BK;
            avr[0] = *reinterpret_cast<const float4*>(A + (rowBase + rA0) * GK + k0 + kqA0 * 4);
            avr[1] = *reinterpret_cast<const float4*>(A + (rowBase + rA1) * GK + k0 + kqA1 * 4);
            #pragma unroll
            for (int i = 0; i < 12; i++) {
                int e = tid + i * 256;
                int k = e / 96;
                int n = e - k * 96;
                bvr[i] = __ldg(Bsrc + (k0 + k) * ldB + colBase + n);
            }
        }

        #pragma unroll
        for (int k = 0; k < BK; k++) {
            float4 av = *reinterpret_cast<const float4*>(&As[cur][k][ty * 4]);
            float a[4] = {av.x, av.y, av.z, av.w};
            float bv[6];
            float2 b0 = *reinterpret_cast<const float2*>(&Bs[cur][k][tx * 6 + 0]);
            float2 b1 = *reinterpret_cast<const float2*>(&Bs[cur][k][tx * 6 + 2]);
            float2 b2 = *reinterpret_cast<const float2*>(&Bs[cur][k][tx * 6 + 4]);
            bv[0] = b0.x; bv[1] = b0.y; bv[2] = b1.x; bv[3] = b1.y; bv[4] = b2.x; bv[5] = b2.y;
            #pragma unroll
            for (int i = 0; i < 4; i++)
                #pragma unroll
                for (int j = 0; j < 6; j++)
                    acc[i][j] = fmaf(a[i], bv[j], acc[i][j]);
        }

        if (t + 1 < NT) {
            const int nxt = 1 - cur;
            As[nxt][kqA0 * 4 + 0][rA0] = avr[0].x;
            As[nxt][kqA0 * 4 + 1][rA0] = avr[0].y;
            As[nxt][kqA0 * 4 + 2][rA0] = avr[0].z;
            As[nxt][kqA0 * 4 + 3][rA0] = avr[0].w;
            As[nxt][kqA1 * 4 + 0][rA1] = avr[1].x;
            As[nxt][kqA1 * 4 + 1][rA1] = avr[1].y;
            As[nxt][kqA1 * 4 + 2][rA1] = avr[1].z;
            As[nxt][kqA1 * 4 + 3][rA1] = avr[1].w;
            #pragma unroll
            for (int i = 0; i < 12; i++) {
                int e = tid + i * 256;
                int k = e / 96;
                int n = e - k * 96;
                Bs[nxt][k][n] = bvr[i];
            }
        }
        __syncthreads();
    }

    // ---- epilogue: add bias, write to g_raw
    #pragma unroll
    for (int i = 0; i < 4; i++) {
        int r = rowBase + ty * 4 + i;
        #pragma unroll
        for (int j = 0; j < 6; j++) {
            int n = tx * 6 + j;
            g_raw[r * NRAW + nGlobalBase + n] = acc[i][j] + __ldg(bias + colBase + n);
        }
    }
}

// ---------------------------------------------------------------------------
// Kernel 2: fused softmax + location transform + bilinear gather + weighted
// sum. R8 structure (4 queries x 64 threads, float4 channels), but Phase D's
// corner loads are branch-free predicated LDG.128 (ldg_cond) and the point
// loop is fully unrolled -> ptxas can keep many loads in flight instead of
// fencing at each `if`.
// ---------------------------------------------------------------------------
__global__ __launch_bounds__(256) void dfine_sample_kernel(
    const float* __restrict__ refp,   // (32,300,1,4)
    const float* __restrict__ value,  // input_flatten (32, 8400, 256)
    float* __restrict__ out)          // (32,300,256)
{
    __shared__ int   sOffs[4][96][4];  // absolute spatial index (0..8399) or -1
    __shared__ float sWts[4][96][4];   // bilinear weights * softmax weight
    __shared__ float sLog[4][96];      // attn logits -> probabilities

    const int tid  = threadIdx.x;
    const int row0 = blockIdx.x * 4;   // 300 % 4 == 0 -> never straddles a batch

    // ---- Phase A: per-(query,head,point) address/weight precompute
    #pragma unroll
    for (int e = tid; e < 384; e += 256) {
        int qi = e / 96, j = e % 96;       // j = h*12 + pt
        int row = row0 + qi;
        const float* raw = g_raw + (size_t)row * NRAW;
        float rx = __ldg(refp + row * 4 + 0);
        float ry = __ldg(refp + row * 4 + 1);
        float rw = __ldg(refp + row * 4 + 2);
        float rh = __ldg(refp + row * 4 + 3);
        float ox = raw[2 * j + 0];
        float oy = raw[2 * j + 1];
        sLog[qi][j] = raw[192 + j];

        int pt  = j % 12;
        int lvl = pt >> 2;
        int   W    = (lvl == 0) ? 80 : (lvl == 1) ? 40 : 20;  // H == W
        int   loff = (lvl == 0) ? 0  : (lvl == 1) ? 6400 : 8000;
        float Wf   = (float)W;
        // pscale=1/4, OFFSET_SCALE=0.5 -> 0.125; pixel = loc*W - 0.5
        float ix = (rx + ox * 0.125f * rw) * Wf - 0.5f;
        float iy = (ry + oy * 0.125f * rh) * Wf - 0.5f;
        float fx0 = floorf(ix), fy0 = floorf(iy);
        float fx = ix - fx0, fy = iy - fy0;
        int x0 = (int)fx0, y0 = (int)fy0;
        int x1 = x0 + 1,   y1 = y0 + 1;
        bool vx0 = (unsigned)x0 < (unsigned)W;
        bool vx1 = (unsigned)x1 < (unsigned)W;
        bool vy0 = (unsigned)y0 < (unsigned)W;
        bool vy1 = (unsigned)y1 < (unsigned)W;
        sOffs[qi][j][0] = (vx0 && vy0) ? (loff + y0 * W + x0) : -1;
        sOffs[qi][j][1] = (vx1 && vy0) ? (loff + y0 * W + x1) : -1;
        sOffs[qi][j][2] = (vx0 && vy1) ? (loff + y1 * W + x0) : -1;
        sOffs[qi][j][3] = (vx1 && vy1) ? (loff + y1 * W + x1) : -1;
        float gx = 1.0f - fx, gy = 1.0f - fy;
        sWts[qi][j][0] = gx * gy;
        sWts[qi][j][1] = fx * gy;
        sWts[qi][j][2] = gx * fy;
        sWts[qi][j][3] = fx * fy;
    }
    __syncthreads();

    // ---- Phase B: per-(query,head) softmax over 12 points (in place)
    if (tid < 32) {
        int qi = tid >> 3, h = tid & 7;
        float* L = &sLog[qi][h * 12];
        float m = -1e30f;
        #pragma unroll
        for (int p = 0; p < 12; p++) m = fmaxf(m, L[p]);
        float s = 0.0f;
        #pragma unroll
        for (int p = 0; p < 12; p++) { float ev = expf(L[p] - m); L[p] = ev; s += ev; }
        float inv = 1.0f / s;
        #pragma unroll
        for (int p = 0; p < 12; p++) L[p] *= inv;
    }
    __syncthreads();

    // ---- Phase C: fold softmax weight into bilinear weights
    #pragma unroll
    for (int e = tid; e < 384; e += 256) {
        int qi = e / 96, j = e % 96;
        float w = sLog[qi][j];
        sWts[qi][j][0] *= w;
        sWts[qi][j][1] *= w;
        sWts[qi][j][2] *= w;
        sWts[qi][j][3] *= w;
    }
    __syncthreads();

    // ---- Phase D: branch-free gather + accumulate.
    const int qi   = tid >> 6;         // query within block
    const int lane = tid & 63;         // channel-quad index 0..63
    const int h    = lane >> 3;        // head (8 channel-quads per head)
    const int row  = row0 + qi;
    const int b    = row / 300;

    const float4* __restrict__ vb =
        (const float4*)value + (size_t)b * 8400 * 64 + h * 8 + (lane & 7);

    float4 acc = make_float4(0.0f, 0.0f, 0.0f, 0.0f);
    #pragma unroll
    for (int pt = 0; pt < 12; pt++) {
        int j = h * 12 + pt;
        int4   o = *reinterpret_cast<const int4*>(sOffs[qi][j]);
        float4 w = *reinterpret_cast<const float4*>(sWts[qi][j]);
        // Predicated @p LDG.128: zero result when offset < 0, no branch.
        float4 v0 = ldg_cond(vb + (size_t)o.x * 64, o.x);
        float4 v1 = ldg_cond(vb + (size_t)o.y * 64, o.y);
        float4 v2 = ldg_cond(vb + (size_t)o.z * 64, o.z);
        float4 v3 = ldg_cond(vb + (size_t)o.w * 64, o.w);
        acc.x += w.x * v0.x; acc.y += w.x * v0.y; acc.z += w.x * v0.z; acc.w += w.x * v0.w;
        acc.x += w.y * v1.x; acc.y += w.y * v1.y; acc.z += w.y * v1.z; acc.w += w.y * v1.w;
        acc.x += w.z * v2.x; acc.y += w.z * v2.y; acc.z += w.z * v2.z; acc.w += w.z * v2.w;
        acc.x += w.w * v3.x; acc.y += w.w * v3.y; acc.z += w.w * v3.z; acc.w += w.w * v3.w;
    }

    reinterpret_cast<float4*>(out)[(size_t)row * 64 + lane] = acc;
}

// ---------------------------------------------------------------------------
// Launch: plain serialized two-kernel schedule (overlap experiments R11/R16
// proved net-negative: sub-machine-fill chunks cost more than overlap gains).
// Inputs in metadata order:
//   0 query (32,300,256) f32        1 reference_points (32,300,1,4) f32
//   2 input_flatten (32,8400,256)   3 W_off (256,192)   4 b_off (192)
//   5 W_attn (256,96)               6 b_attn (96)
// Output: (32,300,256) f32
// ---------------------------------------------------------------------------
extern "C" void kernel_launch(void* const* d_in, const int* in_sizes, int n_in,
                              void* d_out, int out_size) {
    const float* query = (const float*)d_in[0];
    const float* refp  = (const float*)d_in[1];
    const float* value = (const float*)d_in[2];
    const float* Woff  = (const float*)d_in[3];
    const float* boff  = (const float*)d_in[4];
    const float* Wattn = (const float*)d_in[5];
    const float* battn = (const float*)d_in[6];
    float* out = (float*)d_out;

    dim3 ggrid(GM / BM, 3);  // 150 x 3 = 450 blocks
    dfine_gemm_kernel<<<ggrid, 256>>>(query, Woff, boff, Wattn, battn);
    dfine_sample_kernel<<<GM / 4, 256>>>(refp, value, out);
}